// round 14
// baseline (speedup 1.0000x reference)
#include <cuda_runtime.h>
#include <math.h>
#include <stdint.h>

// ============================================================================
// TemporalSamplingUpSampler — 2-phase (round-6 structure + A-transpose):
//   1) expand_kernel<<<128,256>>>: per-block fused plan (softmax, rint,
//      prefix-sum, lmax) + column expansion -> d_w[T], d_k[T].
//      ALSO cooperatively writes At[k][c] = A[c][k] (each block owns a
//      distinct k-slice; 256KB total, negligible).
//   2) fill_kernel: out[c,tt] = A[c,k[tt]] * w[tt]. Fast path now loads the
//      8 per-c A-values as TWO float4 loads from At (vs 8 scalar LDGs),
//      cutting LSU issue ~19% (kernel is LSU-issue-bound per R12 evidence).
//      Load-4/store-4 grouping keeps registers ~round-6 level.
// ============================================================================

#define MAX_K 1024
#define MAX_C 1024
#define MAX_T (1 << 18)

__device__ float d_w[MAX_T];
__device__ int   d_k[MAX_T];
__device__ __align__(16) float d_At[MAX_K * MAX_C];   // At[k][c], row stride C

// ---------------------------------------------------------------------------
// Expand kernel with fused block-parallel plan (round-6) + A transpose.
// ---------------------------------------------------------------------------
__global__ void __launch_bounds__(256) expand_kernel(
    const float* __restrict__ L, const float* __restrict__ A,
    int K, int T, int C, float Tf)
{
    __shared__ float s_Lp[MAX_K];
    __shared__ int   s_cum[MAX_K + 1];
    __shared__ float sred[32];
    __shared__ int   sscan[32];
    __shared__ int   s_total;
    __shared__ float s_lmax;

    const int t    = threadIdx.x;
    const int lane = t & 31;
    const int warp = t >> 5;
    const int nw   = blockDim.x >> 5;                     // 8
    const int EPT  = (K + blockDim.x - 1) / blockDim.x;   // 1 for K=256
    const int base = t * EPT;

    // ---- A transpose slice: block owns k in [bk0, bk1) ----
    {
        const int kpb = (K + gridDim.x - 1) / gridDim.x;
        const int bk0 = blockIdx.x * kpb;
        int bk1 = bk0 + kpb; if (bk1 > K) bk1 = K;
        for (int k = bk0; k < bk1; ++k) {
            for (int c = t; c < C; c += blockDim.x) {
                d_At[(size_t)k * C + c] = A[(size_t)c * K + k];
            }
        }
    }

    float lv[4];
#pragma unroll
    for (int i = 0; i < 4; i++) {
        int k = base + i;
        lv[i] = (i < EPT && k < K) ? __ldg(L + k) : -INFINITY;
    }

    // block max(L)
    float mx = fmaxf(fmaxf(lv[0], lv[1]), fmaxf(lv[2], lv[3]));
    for (int o = 16; o; o >>= 1) mx = fmaxf(mx, __shfl_xor_sync(0xffffffffu, mx, o));
    if (lane == 0) sred[warp] = mx;
    __syncthreads();
    if (warp == 0) {
        float v = (lane < nw) ? sred[lane] : -INFINITY;
        for (int o = 16; o; o >>= 1) v = fmaxf(v, __shfl_xor_sync(0xffffffffu, v, o));
        if (lane == 0) sred[0] = v;
    }
    __syncthreads();
    mx = sred[0];
    __syncthreads();

    // block sum(exp)
    float e[4];
    float s = 0.0f;
#pragma unroll
    for (int i = 0; i < 4; i++) {
        int k = base + i;
        e[i] = (i < EPT && k < K) ? expf(lv[i] - mx) : 0.0f;
        s += e[i];
    }
    for (int o = 16; o; o >>= 1) s += __shfl_xor_sync(0xffffffffu, s, o);
    if (lane == 0) sred[warp] = s;
    __syncthreads();
    if (warp == 0) {
        float v = (lane < nw) ? sred[lane] : 0.0f;
        for (int o = 16; o; o >>= 1) v += __shfl_xor_sync(0xffffffffu, v, o);
        if (lane == 0) sred[0] = v;
    }
    __syncthreads();
    const float sum = sred[0];
    __syncthreads();

    // Lp -> smem, r = max(rint(Lp),0), maxLp
    float maxLp = -INFINITY;
    int rr[4];
    int rs = 0;
#pragma unroll
    for (int i = 0; i < 4; i++) {
        int k = base + i;
        if (i < EPT && k < K) {
            float Lp = Tf * __fdiv_rn(e[i], sum);
            s_Lp[k] = Lp;
            maxLp = fmaxf(maxLp, Lp);
            int r = (int)rintf(Lp);        // half-to-even == np.rint
            if (r < 0) r = 0;
            rr[i] = r;
            rs += r;
        } else rr[i] = 0;
    }

    // block max(Lp)
    float mLp = maxLp;
    for (int o = 16; o; o >>= 1) mLp = fmaxf(mLp, __shfl_xor_sync(0xffffffffu, mLp, o));
    if (lane == 0) sred[warp] = mLp;
    __syncthreads();
    if (warp == 0) {
        float v = (lane < nw) ? sred[lane] : -INFINITY;
        for (int o = 16; o; o >>= 1) v = fmaxf(v, __shfl_xor_sync(0xffffffffu, v, o));
        if (lane == 0) sred[0] = v;
    }

    // block scan of rs (two-level shfl)
    int incl = rs;
    for (int o = 1; o < 32; o <<= 1) {
        int v = __shfl_up_sync(0xffffffffu, incl, o);
        if (lane >= o) incl += v;
    }
    if (lane == 31) sscan[warp] = incl;
    __syncthreads();
    if (warp == 0) {
        int v = (lane < nw) ? sscan[lane] : 0;
        for (int o = 1; o < 32; o <<= 1) {
            int u = __shfl_up_sync(0xffffffffu, v, o);
            if (lane >= o) v += u;
        }
        if (lane < nw) sscan[lane] = v;    // inclusive warp totals
    }
    __syncthreads();

    const int warp_excl = (warp == 0) ? 0 : sscan[warp - 1];
    int running = warp_excl + (incl - rs);
#pragma unroll
    for (int i = 0; i < 4; i++) {
        int k = base + i;
        if (i < EPT && k < K) {
            running += rr[i];
            s_cum[k + 1] = running;
        }
    }
    if (t == 0) {
        s_cum[0] = 0;
        s_total  = sscan[nw - 1];
        double dm = (double)sred[0] + 0.5;
        s_lmax = (float)(long long)dm;     // int(max+0.5), trunc==floor (>=0)
    }
    __syncthreads();

    // expansion (4 columns / thread)
    const int tt0 = (blockIdx.x * blockDim.x + threadIdx.x) * 4;
    if (tt0 >= T) return;

    const int   total = s_total;
    const float lmaxf = s_lmax;

    const bool  pow2  = (T & (T - 1)) == 0;
    const int   shift = __ffs(T) - 1;
    const double ratio = (double)total / (double)T;

    float wv[4];
    int   kv[4];

#pragma unroll
    for (int i = 0; i < 4; i++) {
        int tt = tt0 + i;
        if (tt > T - 1) tt = T - 1;

        long long slot;
        if (pow2) {
            slot = ((long long)tt * (long long)total) >> shift;  // exact
        } else {
            slot = (long long)floor((double)tt * ratio);
        }
        if (slot > (long long)(total - 1)) slot = total - 1;
        if (slot < 0) slot = 0;

        int lo = 0, hi = K;
        const int si = (int)slot;
        while (hi - lo > 1) {
            int mid = (lo + hi) >> 1;
            if (s_cum[mid] <= si) lo = mid; else hi = mid;
        }
        const int k = lo;
        const int j = si - s_cum[k];

        const float Lp = s_Lp[k];
        const float x  = __fadd_rn(__fdiv_rn(__fadd_rn(__fmul_rn(2.0f, (float)j), 1.0f), lmaxf), -1.0f);
        const float sc = __fdiv_rn(lmaxf, Lp);
        const float tl = __fdiv_rn(__fadd_rn(lmaxf, -Lp), Lp);
        const float xs = __fadd_rn(__fmul_rn(sc, x), tl);
        const float p  = __fmul_rn(__fadd_rn(__fmul_rn(__fadd_rn(xs, 1.0f), 100.0f), -1.0f), 0.5f);
        const float p0 = floorf(p);
        const float w1 = __fadd_rn(p, -p0);
        const float in0 = (p0 >=  0.0f && p0 <= 99.0f) ? 1.0f : 0.0f;
        const float in1 = (p0 >= -1.0f && p0 <= 98.0f) ? 1.0f : 0.0f;
        wv[i] = __fadd_rn(__fmul_rn(__fadd_rn(1.0f, -w1), in0), __fmul_rn(w1, in1));
        kv[i] = k;
    }

    if (tt0 + 3 < T) {
        *reinterpret_cast<float4*>(&d_w[tt0]) = make_float4(wv[0], wv[1], wv[2], wv[3]);
        *reinterpret_cast<int4*>  (&d_k[tt0]) = make_int4(kv[0], kv[1], kv[2], kv[3]);
    } else {
        for (int i = 0; i < 4 && tt0 + i < T; i++) {
            d_w[tt0 + i] = wv[i];
            d_k[tt0 + i] = kv[i];
        }
    }
}

// ---------------------------------------------------------------------------
// Fill kernel (hot). Round-6 shape; fast path reads A-values as two float4
// loads from d_At (requires c0%4==0 and full 8-row tile).
// ---------------------------------------------------------------------------
__global__ void __launch_bounds__(256) fill_kernel(
    const float* __restrict__ A,
    float* __restrict__ out,
    int K, int T, int C, int c_per_block)
{
    const int tt0 = (blockIdx.x * blockDim.x + threadIdx.x) * 4;
    if (tt0 >= T) return;

    const bool vec = (tt0 + 3 < T);

    float4 w;
    int4   k;
    if (vec) {
        w = *reinterpret_cast<const float4*>(&d_w[tt0]);
        k = *reinterpret_cast<const int4*>  (&d_k[tt0]);
    } else {
        w = make_float4(d_w[tt0], 0.f, 0.f, 0.f);
        k = make_int4(d_k[tt0], 0, 0, 0);
        if (tt0 + 1 < T) { w.y = d_w[tt0 + 1]; k.y = d_k[tt0 + 1]; }
        if (tt0 + 2 < T) { w.z = d_w[tt0 + 2]; k.z = d_k[tt0 + 2]; }
    }

    const int c0 = blockIdx.y * c_per_block;
    int c1 = c0 + c_per_block;
    if (c1 > C) c1 = C;

    // k monotone non-decreasing: ends equal => all four equal.
    const bool same = (k.x == k.w);
    const bool full = (c0 + 8 <= C) && (c_per_block == 8) && ((c0 & 3) == 0);

    if (same & vec & full) {
        // two float4 loads of At[k][c0..c0+7] replace 8 scalar LDGs
        const float4* Atp = reinterpret_cast<const float4*>(d_At + (size_t)k.x * C + c0);
        float* op = out + (size_t)c0 * (size_t)T + tt0;

        float4 a = Atp[0];
        __stcs(reinterpret_cast<float4*>(op), make_float4(a.x*w.x, a.x*w.y, a.x*w.z, a.x*w.w)); op += T;
        __stcs(reinterpret_cast<float4*>(op), make_float4(a.y*w.x, a.y*w.y, a.y*w.z, a.y*w.w)); op += T;
        __stcs(reinterpret_cast<float4*>(op), make_float4(a.z*w.x, a.z*w.y, a.z*w.z, a.z*w.w)); op += T;
        __stcs(reinterpret_cast<float4*>(op), make_float4(a.w*w.x, a.w*w.y, a.w*w.z, a.w*w.w)); op += T;
        a = Atp[1];
        __stcs(reinterpret_cast<float4*>(op), make_float4(a.x*w.x, a.x*w.y, a.x*w.z, a.x*w.w)); op += T;
        __stcs(reinterpret_cast<float4*>(op), make_float4(a.y*w.x, a.y*w.y, a.y*w.z, a.y*w.w)); op += T;
        __stcs(reinterpret_cast<float4*>(op), make_float4(a.z*w.x, a.z*w.y, a.z*w.z, a.z*w.w)); op += T;
        __stcs(reinterpret_cast<float4*>(op), make_float4(a.w*w.x, a.w*w.y, a.w*w.z, a.w*w.w));
    } else {
        for (int c = c0; c < c1; ++c) {
            const float* Ar = A + (size_t)c * (size_t)K;
            float4 o;
            o.x = __ldg(Ar + k.x) * w.x;
            o.y = __ldg(Ar + k.y) * w.y;
            o.z = __ldg(Ar + k.z) * w.z;
            o.w = __ldg(Ar + k.w) * w.w;
            float* op = out + (size_t)c * (size_t)T + tt0;
            if (vec) {
                __stcs(reinterpret_cast<float4*>(op), o);
            } else {
                if (tt0     < T) op[0] = o.x;
                if (tt0 + 1 < T) op[1] = o.y;
                if (tt0 + 2 < T) op[2] = o.z;
                if (tt0 + 3 < T) op[3] = o.w;
            }
        }
    }
}

// ---------------------------------------------------------------------------
extern "C" void kernel_launch(void* const* d_in, const int* in_sizes, int n_in,
                              void* d_out, int out_size)
{
    const float* A = (const float*)d_in[0];   // [C, K]
    const float* L = (const float*)d_in[1];   // [K]

    const int K = in_sizes[1];
    const int C = in_sizes[0] / K;
    const int T = out_size / C;               // out is [1, C, T]

    const int cols_per_block = 256 * 4;
    const int gx = (T + cols_per_block - 1) / cols_per_block;

    expand_kernel<<<gx, 256>>>(L, A, K, T, C, (float)T);

    const int c_per_block = 8;
    dim3 grid(gx, (C + c_per_block - 1) / c_per_block);
    fill_kernel<<<grid, 256>>>(A, (float*)d_out, K, T, C, c_per_block);
}

// round 15
// speedup vs baseline: 1.0870x; 1.0870x over previous
#include <cuda_runtime.h>
#include <math.h>
#include <stdint.h>

// ============================================================================
// TemporalSamplingUpSampler — 2-phase, round-6 kernels EXACTLY, plus PDL:
//   expand_kernel<<<128,256>>>  : fused block-parallel plan + column
//                                 expansion -> d_w[T], d_k[T]; triggers
//                                 programmatic launch completion at the end.
//   fill_kernel<<<(128,32),256>>>: launched with programmatic stream
//                                 serialization; calls
//                                 cudaGridDependencySynchronize() before
//                                 reading the plan. Launch/schedule/prologue
//                                 overlaps expand -> hides the ~3-6us gap.
// ============================================================================

#define MAX_K 1024
#define MAX_T (1 << 18)

__device__ float d_w[MAX_T];
__device__ int   d_k[MAX_T];

// ---------------------------------------------------------------------------
// Expand kernel with fused block-parallel plan (round-6, unchanged body).
// ---------------------------------------------------------------------------
__global__ void __launch_bounds__(256) expand_kernel(
    const float* __restrict__ L, int K, int T, float Tf)
{
    __shared__ float s_Lp[MAX_K];
    __shared__ int   s_cum[MAX_K + 1];
    __shared__ float sred[32];
    __shared__ int   sscan[32];
    __shared__ int   s_total;
    __shared__ float s_lmax;

    const int t    = threadIdx.x;
    const int lane = t & 31;
    const int warp = t >> 5;
    const int nw   = blockDim.x >> 5;                     // 8
    const int EPT  = (K + blockDim.x - 1) / blockDim.x;   // 1 for K=256
    const int base = t * EPT;

    float lv[4];
#pragma unroll
    for (int i = 0; i < 4; i++) {
        int k = base + i;
        lv[i] = (i < EPT && k < K) ? __ldg(L + k) : -INFINITY;
    }

    // block max(L)
    float mx = fmaxf(fmaxf(lv[0], lv[1]), fmaxf(lv[2], lv[3]));
    for (int o = 16; o; o >>= 1) mx = fmaxf(mx, __shfl_xor_sync(0xffffffffu, mx, o));
    if (lane == 0) sred[warp] = mx;
    __syncthreads();
    if (warp == 0) {
        float v = (lane < nw) ? sred[lane] : -INFINITY;
        for (int o = 16; o; o >>= 1) v = fmaxf(v, __shfl_xor_sync(0xffffffffu, v, o));
        if (lane == 0) sred[0] = v;
    }
    __syncthreads();
    mx = sred[0];
    __syncthreads();

    // block sum(exp)
    float e[4];
    float s = 0.0f;
#pragma unroll
    for (int i = 0; i < 4; i++) {
        int k = base + i;
        e[i] = (i < EPT && k < K) ? expf(lv[i] - mx) : 0.0f;
        s += e[i];
    }
    for (int o = 16; o; o >>= 1) s += __shfl_xor_sync(0xffffffffu, s, o);
    if (lane == 0) sred[warp] = s;
    __syncthreads();
    if (warp == 0) {
        float v = (lane < nw) ? sred[lane] : 0.0f;
        for (int o = 16; o; o >>= 1) v += __shfl_xor_sync(0xffffffffu, v, o);
        if (lane == 0) sred[0] = v;
    }
    __syncthreads();
    const float sum = sred[0];
    __syncthreads();

    // Lp -> smem, r = max(rint(Lp),0), maxLp
    float maxLp = -INFINITY;
    int rr[4];
    int rs = 0;
#pragma unroll
    for (int i = 0; i < 4; i++) {
        int k = base + i;
        if (i < EPT && k < K) {
            float Lp = Tf * __fdiv_rn(e[i], sum);
            s_Lp[k] = Lp;
            maxLp = fmaxf(maxLp, Lp);
            int r = (int)rintf(Lp);        // half-to-even == np.rint
            if (r < 0) r = 0;
            rr[i] = r;
            rs += r;
        } else rr[i] = 0;
    }

    // block max(Lp)
    float mLp = maxLp;
    for (int o = 16; o; o >>= 1) mLp = fmaxf(mLp, __shfl_xor_sync(0xffffffffu, mLp, o));
    if (lane == 0) sred[warp] = mLp;
    __syncthreads();
    if (warp == 0) {
        float v = (lane < nw) ? sred[lane] : -INFINITY;
        for (int o = 16; o; o >>= 1) v = fmaxf(v, __shfl_xor_sync(0xffffffffu, v, o));
        if (lane == 0) sred[0] = v;
    }

    // block scan of rs (two-level shfl)
    int incl = rs;
    for (int o = 1; o < 32; o <<= 1) {
        int v = __shfl_up_sync(0xffffffffu, incl, o);
        if (lane >= o) incl += v;
    }
    if (lane == 31) sscan[warp] = incl;
    __syncthreads();
    if (warp == 0) {
        int v = (lane < nw) ? sscan[lane] : 0;
        for (int o = 1; o < 32; o <<= 1) {
            int u = __shfl_up_sync(0xffffffffu, v, o);
            if (lane >= o) v += u;
        }
        if (lane < nw) sscan[lane] = v;    // inclusive warp totals
    }
    __syncthreads();

    const int warp_excl = (warp == 0) ? 0 : sscan[warp - 1];
    int running = warp_excl + (incl - rs);
#pragma unroll
    for (int i = 0; i < 4; i++) {
        int k = base + i;
        if (i < EPT && k < K) {
            running += rr[i];
            s_cum[k + 1] = running;
        }
    }
    if (t == 0) {
        s_cum[0] = 0;
        s_total  = sscan[nw - 1];
        double dm = (double)sred[0] + 0.5;
        s_lmax = (float)(long long)dm;     // int(max+0.5), trunc==floor (>=0)
    }
    __syncthreads();

    // expansion (4 columns / thread)
    const int tt0 = (blockIdx.x * blockDim.x + threadIdx.x) * 4;
    if (tt0 < T) {
        const int   total = s_total;
        const float lmaxf = s_lmax;

        const bool  pow2  = (T & (T - 1)) == 0;
        const int   shift = __ffs(T) - 1;
        const double ratio = (double)total / (double)T;

        float wv[4];
        int   kv[4];

#pragma unroll
        for (int i = 0; i < 4; i++) {
            int tt = tt0 + i;
            if (tt > T - 1) tt = T - 1;

            long long slot;
            if (pow2) {
                slot = ((long long)tt * (long long)total) >> shift;  // exact
            } else {
                slot = (long long)floor((double)tt * ratio);
            }
            if (slot > (long long)(total - 1)) slot = total - 1;
            if (slot < 0) slot = 0;

            int lo = 0, hi = K;
            const int si = (int)slot;
            while (hi - lo > 1) {
                int mid = (lo + hi) >> 1;
                if (s_cum[mid] <= si) lo = mid; else hi = mid;
            }
            const int k = lo;
            const int j = si - s_cum[k];

            const float Lp = s_Lp[k];
            const float x  = __fadd_rn(__fdiv_rn(__fadd_rn(__fmul_rn(2.0f, (float)j), 1.0f), lmaxf), -1.0f);
            const float sc = __fdiv_rn(lmaxf, Lp);
            const float tl = __fdiv_rn(__fadd_rn(lmaxf, -Lp), Lp);
            const float xs = __fadd_rn(__fmul_rn(sc, x), tl);
            const float p  = __fmul_rn(__fadd_rn(__fmul_rn(__fadd_rn(xs, 1.0f), 100.0f), -1.0f), 0.5f);
            const float p0 = floorf(p);
            const float w1 = __fadd_rn(p, -p0);
            const float in0 = (p0 >=  0.0f && p0 <= 99.0f) ? 1.0f : 0.0f;
            const float in1 = (p0 >= -1.0f && p0 <= 98.0f) ? 1.0f : 0.0f;
            wv[i] = __fadd_rn(__fmul_rn(__fadd_rn(1.0f, -w1), in0), __fmul_rn(w1, in1));
            kv[i] = k;
        }

        if (tt0 + 3 < T) {
            *reinterpret_cast<float4*>(&d_w[tt0]) = make_float4(wv[0], wv[1], wv[2], wv[3]);
            *reinterpret_cast<int4*>  (&d_k[tt0]) = make_int4(kv[0], kv[1], kv[2], kv[3]);
        } else {
            for (int i = 0; i < 4 && tt0 + i < T; i++) {
                d_w[tt0 + i] = wv[i];
                d_k[tt0 + i] = kv[i];
            }
        }
    }

#if __CUDA_ARCH__ >= 900
    // Allow the dependent fill grid to begin launching.
    cudaTriggerProgrammaticLaunchCompletion();
#endif
}

// ---------------------------------------------------------------------------
// Fill kernel (hot) — round-6 body, prefixed by the PDL dependency sync.
// ---------------------------------------------------------------------------
__global__ void __launch_bounds__(256) fill_kernel(
    const float* __restrict__ A,
    float* __restrict__ out,
    int K, int T, int C, int c_per_block)
{
    const int tt0 = (blockIdx.x * blockDim.x + threadIdx.x) * 4;

#if __CUDA_ARCH__ >= 900
    // Wait until expand's stores to d_w/d_k are visible.
    cudaGridDependencySynchronize();
#endif

    if (tt0 >= T) return;

    const bool vec = (tt0 + 3 < T);

    float4 w;
    int4   k;
    if (vec) {
        w = *reinterpret_cast<const float4*>(&d_w[tt0]);
        k = *reinterpret_cast<const int4*>  (&d_k[tt0]);
    } else {
        w = make_float4(d_w[tt0], 0.f, 0.f, 0.f);
        k = make_int4(d_k[tt0], 0, 0, 0);
        if (tt0 + 1 < T) { w.y = d_w[tt0 + 1]; k.y = d_k[tt0 + 1]; }
        if (tt0 + 2 < T) { w.z = d_w[tt0 + 2]; k.z = d_k[tt0 + 2]; }
    }

    const int c0 = blockIdx.y * c_per_block;
    int c1 = c0 + c_per_block;
    if (c1 > C) c1 = C;

    // k monotone non-decreasing: ends equal => all four equal.
    const bool same = (k.x == k.w);

    if (same & vec) {
        const float* Ap = A + (size_t)c0 * (size_t)K + k.x;
        float* op = out + (size_t)c0 * (size_t)T + tt0;
#pragma unroll 4
        for (int c = c0; c < c1; ++c) {
            const float a = __ldg(Ap);
            float4 o = make_float4(a * w.x, a * w.y, a * w.z, a * w.w);
            __stcs(reinterpret_cast<float4*>(op), o);
            Ap += K;
            op += T;
        }
    } else {
        for (int c = c0; c < c1; ++c) {
            const float* Ar = A + (size_t)c * (size_t)K;
            float4 o;
            o.x = __ldg(Ar + k.x) * w.x;
            o.y = __ldg(Ar + k.y) * w.y;
            o.z = __ldg(Ar + k.z) * w.z;
            o.w = __ldg(Ar + k.w) * w.w;
            float* op = out + (size_t)c * (size_t)T + tt0;
            if (vec) {
                __stcs(reinterpret_cast<float4*>(op), o);
            } else {
                if (tt0     < T) op[0] = o.x;
                if (tt0 + 1 < T) op[1] = o.y;
                if (tt0 + 2 < T) op[2] = o.z;
                if (tt0 + 3 < T) op[3] = o.w;
            }
        }
    }
}

// ---------------------------------------------------------------------------
extern "C" void kernel_launch(void* const* d_in, const int* in_sizes, int n_in,
                              void* d_out, int out_size)
{
    const float* A = (const float*)d_in[0];   // [C, K]
    const float* L = (const float*)d_in[1];   // [K]

    const int K = in_sizes[1];
    const int C = in_sizes[0] / K;
    const int T = out_size / C;               // out is [1, C, T]

    const int cols_per_block = 256 * 4;
    const int gx = (T + cols_per_block - 1) / cols_per_block;

    expand_kernel<<<gx, 256>>>(L, K, T, (float)T);

    const int c_per_block = 8;
    dim3 grid(gx, (C + c_per_block - 1) / c_per_block);

    // Launch fill with Programmatic Dependent Launch: it may begin
    // scheduling while expand drains; correctness is guaranteed by
    // cudaGridDependencySynchronize() inside fill_kernel.
    cudaLaunchConfig_t cfg = {};
    cfg.gridDim  = grid;
    cfg.blockDim = dim3(256);
    cfg.dynamicSmemBytes = 0;
    cfg.stream = 0;
    cudaLaunchAttribute attrs[1];
    attrs[0].id = cudaLaunchAttributeProgrammaticStreamSerialization;
    attrs[0].val.programmaticStreamSerializationAllowed = 1;
    cfg.attrs = attrs;
    cfg.numAttrs = 1;

    cudaError_t err = cudaLaunchKernelEx(&cfg, fill_kernel,
                                         A, (float*)d_out, K, T, C, c_per_block);
    if (err != cudaSuccess) {
        // Fallback: plain serialized launch (round-6 behavior).
        fill_kernel<<<grid, 256>>>(A, (float*)d_out, K, T, C, c_per_block);
    }
}